// round 2
// baseline (speedup 1.0000x reference)
#include <cuda_runtime.h>
#include <math.h>

// Problem constants (from reference): N=100000, D=128, E=1600000
#define EMAX 1600000
#define NB   1184          // 148 SMs * 8 blocks
#define TPB  256
#define WPB  (TPB / 32)
#define NWARPS (NB * WPB)
#define NTHREADS (NB * TPB)

// Scratch (static device globals — no allocation)
__device__ float  g_lik[EMAX];      // likelihood, later reused for sigmoid
__device__ double g_part1[NB];      // per-block sum(lik)
__device__ double g_part2[NB];      // per-block sum(lik^2)
__device__ double g_part3[NB];      // per-block sum(sigmoid)
__device__ float  g_scal[3];        // mu, inv_std, inv_mean_ew

// ---------------------------------------------------------------------------
// K1: gather embeddings, squared distance, likelihood, partial stats.
// One warp per edge per iteration; lane l handles float4 #l of the 128-dim row.
// ---------------------------------------------------------------------------
__global__ __launch_bounds__(TPB) void k_edge(
    const float* __restrict__ src, const float* __restrict__ dst,
    const int* __restrict__ gr, int E, int Nnodes)
{
    const int lane = threadIdx.x & 31;
    const int wblk = threadIdx.x >> 5;
    const int gwarp = blockIdx.x * WPB + wblk;

    const float4* __restrict__ src4 = (const float4*)src;
    const float4* __restrict__ dst4 = (const float4*)dst;

    double s1 = 0.0, s2 = 0.0;

    for (int e = gwarp; e < E; e += NWARPS) {
        int si = 0, di = 0;
        if (lane == 0) {
            si = __ldg(gr + e);
            di = __ldg(gr + (size_t)E + e);
        }
        si = __shfl_sync(0xffffffffu, si, 0);
        di = __shfl_sync(0xffffffffu, di, 0);
        // defensive clamp (turns a bad dtype/layout guess into rel_err, not a crash)
        si = min(max(si, 0), Nnodes - 1);
        di = min(max(di, 0), Nnodes - 1);

        float4 a = __ldg(src4 + (size_t)si * 32 + lane);
        float4 b = __ldg(dst4 + (size_t)di * 32 + lane);
        float dx = a.x - b.x, dy = a.y - b.y, dz = a.z - b.z, dw = a.w - b.w;
        float s = fmaf(dx, dx, fmaf(dy, dy, fmaf(dz, dz, dw * dw)));

        #pragma unroll
        for (int o = 16; o; o >>= 1)
            s += __shfl_xor_sync(0xffffffffu, s, o);

        if (lane == 0) {
            float lik = -logf(fmaxf(s, 1e-12f));
            g_lik[e] = lik;
            s1 += (double)lik;
            s2 += (double)lik * (double)lik;
        }
    }

    __shared__ double sh1[WPB], sh2[WPB];
    if (lane == 0) { sh1[wblk] = s1; sh2[wblk] = s2; }
    __syncthreads();
    if (threadIdx.x == 0) {
        double t1 = 0.0, t2 = 0.0;
        #pragma unroll
        for (int i = 0; i < WPB; i++) { t1 += sh1[i]; t2 += sh2[i]; }
        g_part1[blockIdx.x] = t1;
        g_part2[blockIdx.x] = t2;
    }
}

// ---------------------------------------------------------------------------
// K2: finalize mu, inv_std (single block, deterministic tree reduce)
// ---------------------------------------------------------------------------
__global__ __launch_bounds__(TPB) void k_stats(int E)
{
    __shared__ double sh1[TPB], sh2[TPB];
    double t1 = 0.0, t2 = 0.0;
    for (int i = threadIdx.x; i < NB; i += TPB) { t1 += g_part1[i]; t2 += g_part2[i]; }
    sh1[threadIdx.x] = t1; sh2[threadIdx.x] = t2;
    __syncthreads();
    for (int s = TPB / 2; s; s >>= 1) {
        if (threadIdx.x < s) {
            sh1[threadIdx.x] += sh1[threadIdx.x + s];
            sh2[threadIdx.x] += sh2[threadIdx.x + s];
        }
        __syncthreads();
    }
    if (threadIdx.x == 0) {
        double mu  = sh1[0] / (double)E;
        double var = sh2[0] / (double)E - mu * mu;
        g_scal[0] = (float)mu;
        g_scal[1] = (float)rsqrt(var + 1e-5);
    }
}

// ---------------------------------------------------------------------------
// K3: logits + sigmoid + partial sigmoid-sum; also graph -> float copy.
// Assumed output layout (float32): [graph (2E)] [edge_weights (E)] [logits (E)]
// All stores guarded by out_size so a wrong layout guess shows as rel_err.
// ---------------------------------------------------------------------------
__global__ __launch_bounds__(TPB) void k_logits(
    const int* __restrict__ gr,
    const float* __restrict__ bw, const float* __restrict__ bb,
    float* __restrict__ out, int E, long long out_size)
{
    const float mu  = g_scal[0];
    const float inv = g_scal[1];
    const float w   = __ldg(bw);
    const float b   = __ldg(bb);

    const long long logit_base = 3LL * E;
    const int tid = blockIdx.x * TPB + threadIdx.x;
    double s = 0.0;

    for (int e = tid; e < E; e += NTHREADS) {
        float lik = g_lik[e];
        float lg  = fmaf(w * (lik - mu), inv, b);
        if (logit_base + e < out_size) out[logit_base + e] = lg;
        float sig = 1.0f / (1.0f + expf(-lg));
        g_lik[e] = sig;        // reuse scratch
        s += (double)sig;
    }

    const int E2 = 2 * E;
    for (int i = tid; i < E2 && i < out_size; i += NTHREADS)
        out[i] = (float)__ldg(gr + i);

    __shared__ double sh[TPB];
    sh[threadIdx.x] = s;
    __syncthreads();
    for (int st = TPB / 2; st; st >>= 1) {
        if (threadIdx.x < st) sh[threadIdx.x] += sh[threadIdx.x + st];
        __syncthreads();
    }
    if (threadIdx.x == 0) g_part3[blockIdx.x] = sh[0];
}

// ---------------------------------------------------------------------------
// K4: finalize inv_mean of edge weights
// ---------------------------------------------------------------------------
__global__ __launch_bounds__(TPB) void k_mean(int E)
{
    __shared__ double sh[TPB];
    double t = 0.0;
    for (int i = threadIdx.x; i < NB; i += TPB) t += g_part3[i];
    sh[threadIdx.x] = t;
    __syncthreads();
    for (int s = TPB / 2; s; s >>= 1) {
        if (threadIdx.x < s) sh[threadIdx.x] += sh[threadIdx.x + s];
        __syncthreads();
    }
    if (threadIdx.x == 0) g_scal[2] = (float)((double)E / sh[0]);
}

// ---------------------------------------------------------------------------
// K5: normalized edge weights
// ---------------------------------------------------------------------------
__global__ __launch_bounds__(TPB) void k_ew(float* __restrict__ out, int E,
                                            long long out_size)
{
    const float inv_mean = g_scal[2];
    const long long ew_base = 2LL * E;
    for (int e = blockIdx.x * TPB + threadIdx.x; e < E; e += NTHREADS)
        if (ew_base + e < out_size) out[ew_base + e] = g_lik[e] * inv_mean;
}

// ---------------------------------------------------------------------------
extern "C" void kernel_launch(void* const* d_in, const int* in_sizes, int n_in,
                              void* d_out, int out_size)
{
    const float* src = (const float*)d_in[0];
    const float* dst = (const float*)d_in[1];
    const int*   gr  = (const int*)d_in[2];
    const float* bw  = (const float*)d_in[3];
    const float* bb  = (const float*)d_in[4];
    float* out = (float*)d_out;

    const int E = in_sizes[2] / 2;
    const int Nnodes = in_sizes[0] / 128;
    const long long osz = (long long)out_size;

    k_edge  <<<NB, TPB>>>(src, dst, gr, E, Nnodes);
    k_stats <<<1,  TPB>>>(E);
    k_logits<<<NB, TPB>>>(gr, bw, bb, out, E, osz);
    k_mean  <<<1,  TPB>>>(E);
    k_ew    <<<NB, TPB>>>(out, E, osz);
}

// round 3
// speedup vs baseline: 2.3944x; 2.3944x over previous
#include <cuda_runtime.h>
#include <cuda_fp16.h>
#include <math.h>

// Problem constants: N=100000, D=128, E=1600000
#define NMAX 100000
#define DD   128
#define EMAX 1600000
#define NB   1184
#define TPB  256
#define WPB  (TPB / 32)
#define NWARPS (NB * WPB)
#define NTHREADS (NB * TPB)

// Static device scratch (no allocations)
__device__ __half g_srch[NMAX * DD];   // fp16 copy of src embeddings
__device__ __half g_dsth[NMAX * DD];   // fp16 copy of dst embeddings
__device__ float  g_lik[EMAX];         // likelihood, later reused for sigmoid
__device__ double g_p1[NB], g_p2[NB], g_p3[NB];

// ---------------------------------------------------------------------------
// K0: fp32 -> fp16 table conversion (streaming, DRAM-bound)
// ---------------------------------------------------------------------------
__global__ __launch_bounds__(TPB) void k_conv(
    const float* __restrict__ src, const float* __restrict__ dst, int total)
{
    const int nt4 = total >> 2;
    const float4* __restrict__ s4 = (const float4*)src;
    const float4* __restrict__ d4 = (const float4*)dst;
    uint2* __restrict__ so = (uint2*)g_srch;
    uint2* __restrict__ dó = (uint2*)g_dsth;

    for (int i = blockIdx.x * TPB + threadIdx.x; i < nt4; i += NTHREADS) {
        float4 v = __ldcs(s4 + i);
        union { __half2 h; unsigned u; } c0, c1;
        c0.h = __floats2half2_rn(v.x, v.y);
        c1.h = __floats2half2_rn(v.z, v.w);
        so[i] = make_uint2(c0.u, c1.u);

        float4 w = __ldcs(d4 + i);
        c0.h = __floats2half2_rn(w.x, w.y);
        c1.h = __floats2half2_rn(w.z, w.w);
        dó[i] = make_uint2(c0.u, c1.u);
    }
}

// ---------------------------------------------------------------------------
// K1: gather + squared distance + likelihood + partial stats + graph->float.
// Warp processes 32 edges per chunk: indices loaded coalesced (1/lane),
// broadcast from registers; lane j keeps edge j's likelihood -> coalesced store.
// ---------------------------------------------------------------------------
__global__ __launch_bounds__(TPB) void k_edge(
    const int* __restrict__ gr, float* __restrict__ out, int E, int Nn)
{
    const int lane  = threadIdx.x & 31;
    const int gwarp = (blockIdx.x * TPB + threadIdx.x) >> 5;

    const uint2* __restrict__ sh2 = (const uint2*)g_srch;  // row = 32 uint2 (256B)
    const uint2* __restrict__ dh2 = (const uint2*)g_dsth;

    double a1 = 0.0, a2 = 0.0;

    for (int base = gwarp * 32; base < E; base += NWARPS * 32) {
        const int m = min(32, E - base);
        const int e = base + lane;

        int si = 0, di = 0;
        if (lane < m) {
            si = __ldcs(gr + e);
            di = __ldcs(gr + (size_t)E + e);
            out[e] = (float)si;              // graph row 0 -> float output
            out[(size_t)E + e] = (float)di;  // graph row 1 -> float output
        }
        si = min(max(si, 0), Nn - 1);
        di = min(max(di, 0), Nn - 1);

        float v = 0.0f;
        #pragma unroll 4
        for (int j = 0; j < 32; j++) {
            if (j >= m) break;
            const int s = __shfl_sync(0xffffffffu, si, j);
            const int d = __shfl_sync(0xffffffffu, di, j);

            uint2 av = __ldg(sh2 + (size_t)s * 32 + lane);
            uint2 bv = __ldg(dh2 + (size_t)d * 32 + lane);
            float2 fa0 = __half22float2(*(__half2*)&av.x);
            float2 fa1 = __half22float2(*(__half2*)&av.y);
            float2 fb0 = __half22float2(*(__half2*)&bv.x);
            float2 fb1 = __half22float2(*(__half2*)&bv.y);

            float dx = fa0.x - fb0.x, dy = fa0.y - fb0.y;
            float dz = fa1.x - fb1.x, dw = fa1.y - fb1.y;
            float p = fmaf(dx, dx, fmaf(dy, dy, fmaf(dz, dz, dw * dw)));

            #pragma unroll
            for (int o = 16; o; o >>= 1)
                p += __shfl_xor_sync(0xffffffffu, p, o);

            if (lane == j) v = -__logf(fmaxf(p, 1e-12f));
        }

        if (lane < m) {
            __stcs(g_lik + e, v);
            a1 += (double)v;
            a2 += (double)v * (double)v;
        }
    }

    __shared__ double sh1[TPB], shq[TPB];
    sh1[threadIdx.x] = a1; shq[threadIdx.x] = a2;
    __syncthreads();
    for (int st = TPB / 2; st; st >>= 1) {
        if (threadIdx.x < st) {
            sh1[threadIdx.x] += sh1[threadIdx.x + st];
            shq[threadIdx.x] += shq[threadIdx.x + st];
        }
        __syncthreads();
    }
    if (threadIdx.x == 0) { g_p1[blockIdx.x] = sh1[0]; g_p2[blockIdx.x] = shq[0]; }
}

// ---------------------------------------------------------------------------
// K2: (block-local mu/inv_std finalize) + logits + sigmoid + partial sums
// ---------------------------------------------------------------------------
__global__ __launch_bounds__(TPB) void k_logits(
    const float* __restrict__ bw, const float* __restrict__ bb,
    float* __restrict__ out, int E)
{
    __shared__ double sh1[TPB], shq[TPB];
    double t1 = 0.0, t2 = 0.0;
    for (int i = threadIdx.x; i < NB; i += TPB) { t1 += g_p1[i]; t2 += g_p2[i]; }
    sh1[threadIdx.x] = t1; shq[threadIdx.x] = t2;
    __syncthreads();
    for (int st = TPB / 2; st; st >>= 1) {
        if (threadIdx.x < st) {
            sh1[threadIdx.x] += sh1[threadIdx.x + st];
            shq[threadIdx.x] += shq[threadIdx.x + st];
        }
        __syncthreads();
    }
    __shared__ float s_mu, s_inv;
    if (threadIdx.x == 0) {
        double mu  = sh1[0] / (double)E;
        double var = shq[0] / (double)E - mu * mu;
        s_mu  = (float)mu;
        s_inv = (float)rsqrt(var + 1e-5);
    }
    __syncthreads();

    const float mu = s_mu, inv = s_inv;
    const float w = __ldg(bw), b = __ldg(bb);
    float* __restrict__ out_logit = out + 3LL * E;

    double s = 0.0;
    for (int e = blockIdx.x * TPB + threadIdx.x; e < E; e += NTHREADS) {
        float lik = g_lik[e];
        float lg  = fmaf(w * (lik - mu), inv, b);
        __stcs(out_logit + e, lg);
        float sig = 1.0f / (1.0f + __expf(-lg));
        g_lik[e] = sig;
        s += (double)sig;
    }

    sh1[threadIdx.x] = s;
    __syncthreads();
    for (int st = TPB / 2; st; st >>= 1) {
        if (threadIdx.x < st) sh1[threadIdx.x] += sh1[threadIdx.x + st];
        __syncthreads();
    }
    if (threadIdx.x == 0) g_p3[blockIdx.x] = sh1[0];
}

// ---------------------------------------------------------------------------
// K3: (block-local inv_mean finalize) + normalized edge weights
// ---------------------------------------------------------------------------
__global__ __launch_bounds__(TPB) void k_ew(float* __restrict__ out, int E)
{
    __shared__ double sh[TPB];
    double t = 0.0;
    for (int i = threadIdx.x; i < NB; i += TPB) t += g_p3[i];
    sh[threadIdx.x] = t;
    __syncthreads();
    for (int st = TPB / 2; st; st >>= 1) {
        if (threadIdx.x < st) sh[threadIdx.x] += sh[threadIdx.x + st];
        __syncthreads();
    }
    __shared__ float s_im;
    if (threadIdx.x == 0) s_im = (float)((double)E / sh[0]);
    __syncthreads();

    const float inv_mean = s_im;
    float* __restrict__ out_ew = out + 2LL * E;
    for (int e = blockIdx.x * TPB + threadIdx.x; e < E; e += NTHREADS)
        __stcs(out_ew + e, __ldcs(g_lik + e) * inv_mean);
}

// ---------------------------------------------------------------------------
extern "C" void kernel_launch(void* const* d_in, const int* in_sizes, int n_in,
                              void* d_out, int out_size)
{
    const float* src = (const float*)d_in[0];
    const float* dst = (const float*)d_in[1];
    const int*   gr  = (const int*)d_in[2];
    const float* bw  = (const float*)d_in[3];
    const float* bb  = (const float*)d_in[4];
    float* out = (float*)d_out;

    const int E  = in_sizes[2] / 2;
    const int Nn = in_sizes[0] / DD;
    const int total = min(in_sizes[0], NMAX * DD);

    k_conv  <<<NB, TPB>>>(src, dst, total);
    k_edge  <<<NB, TPB>>>(gr, out, E, Nn);
    k_logits<<<NB, TPB>>>(bw, bb, out, E);
    k_ew    <<<NB, TPB>>>(out, E);
}

// round 4
// speedup vs baseline: 3.1312x; 1.3078x over previous
#include <cuda_runtime.h>
#include <cuda_fp16.h>
#include <math.h>

// Problem constants: N=100000, D=128, E=1600000
#define NMAX 100000
#define DD   128
#define EMAX 1600000
#define NB   1184
#define TPB  256
#define WPB  (TPB / 32)
#define NWARPS (NB * WPB)
#define NTHREADS (NB * TPB)

// Static device scratch (no allocations)
__device__ __half g_srch[NMAX * DD];   // fp16 src table (row = 256 B = 16 uint4)
__device__ __half g_dsth[NMAX * DD];   // fp16 dst table
__device__ float  g_lik[EMAX];         // likelihood, later reused for sigmoid
__device__ double g_p1[NB], g_p2[NB], g_p3[NB];

// ---------------------------------------------------------------------------
// K0: fp32 -> fp16 table conversion (streaming, DRAM-bound)
// ---------------------------------------------------------------------------
__global__ __launch_bounds__(TPB) void k_conv(
    const float* __restrict__ src, const float* __restrict__ dst, int total)
{
    const int nt4 = total >> 2;
    const float4* __restrict__ s4 = (const float4*)src;
    const float4* __restrict__ d4 = (const float4*)dst;
    uint2* __restrict__ so = (uint2*)g_srch;
    uint2* __restrict__ dsto = (uint2*)g_dsth;

    for (int i = blockIdx.x * TPB + threadIdx.x; i < nt4; i += NTHREADS) {
        float4 v = __ldcs(s4 + i);
        union { __half2 h; unsigned u; } c0, c1;
        c0.h = __floats2half2_rn(v.x, v.y);
        c1.h = __floats2half2_rn(v.z, v.w);
        so[i] = make_uint2(c0.u, c1.u);

        float4 w = __ldcs(d4 + i);
        c0.h = __floats2half2_rn(w.x, w.y);
        c1.h = __floats2half2_rn(w.z, w.w);
        dsto[i] = make_uint2(c0.u, c1.u);
    }
}

// ---------------------------------------------------------------------------
// K1: gather + squared distance + likelihood + partial stats + graph->float.
// 16 lanes per edge (uint4 = 16B/lane covers the 256B fp16 row), two edges
// per warp-step. Lane k ends up holding edge base+k's distance; single
// vectorized log per 32-edge chunk.
// ---------------------------------------------------------------------------
__global__ __launch_bounds__(TPB) void k_edge(
    const int* __restrict__ gr, float* __restrict__ out, int E, int Nn)
{
    const int lane  = threadIdx.x & 31;
    const int gwarp = (blockIdx.x * TPB + threadIdx.x) >> 5;
    const int half_sel = lane & 16;      // 0 for lanes 0-15, 16 for 16-31
    const int lane15   = lane & 15;

    const uint4* __restrict__ stab = (const uint4*)g_srch;  // 16 uint4 / row
    const uint4* __restrict__ dtab = (const uint4*)g_dsth;

    double a1 = 0.0, a2 = 0.0;

    for (int base = gwarp * 32; base < E; base += NWARPS * 32) {
        const int m = min(32, E - base);
        const int e = base + lane;

        int si = 0, di = 0;
        if (lane < m) {
            si = __ldcs(gr + e);
            di = __ldcs(gr + (size_t)E + e);
            __stcs(out + e, (float)si);              // graph row 0
            __stcs(out + (size_t)E + e, (float)di);  // graph row 1
        }
        si = min(max(si, 0), Nn - 1);
        di = min(max(di, 0), Nn - 1);

        float acc = 0.0f;   // lane k accumulates edge base+k

        #pragma unroll 4
        for (int t = 0; t < 16; t++) {
            const int srcl = t | half_sel;   // lower half reads lane t, upper lane 16+t
            const int s = __shfl_sync(0xffffffffu, si, srcl);
            const int d = __shfl_sync(0xffffffffu, di, srcl);

            uint4 av = __ldg(stab + (size_t)s * 16 + lane15);
            uint4 bv = __ldg(dtab + (size_t)d * 16 + lane15);
            const __half2* ah = (const __half2*)&av;
            const __half2* bh = (const __half2*)&bv;

            float p = 0.0f;
            #pragma unroll
            for (int i = 0; i < 4; i++) {
                float2 fa = __half22float2(ah[i]);
                float2 fb = __half22float2(bh[i]);
                float dx = fa.x - fb.x, dy = fa.y - fb.y;
                p = fmaf(dx, dx, fmaf(dy, dy, p));
            }

            // reduce within each 16-lane half
            #pragma unroll
            for (int o = 8; o; o >>= 1)
                p += __shfl_xor_sync(0xffffffffu, p, o);

            if (lane15 == t) acc = p;   // lane t gets edge base+t, lane 16+t gets base+16+t
        }

        if (lane < m) {
            float v = -__logf(fmaxf(acc, 1e-12f));
            __stcs(g_lik + e, v);
            a1 += (double)v;
            a2 += (double)v * (double)v;
        }
    }

    __shared__ double sh1[TPB], shq[TPB];
    sh1[threadIdx.x] = a1; shq[threadIdx.x] = a2;
    __syncthreads();
    for (int st = TPB / 2; st; st >>= 1) {
        if (threadIdx.x < st) {
            sh1[threadIdx.x] += sh1[threadIdx.x + st];
            shq[threadIdx.x] += shq[threadIdx.x + st];
        }
        __syncthreads();
    }
    if (threadIdx.x == 0) { g_p1[blockIdx.x] = sh1[0]; g_p2[blockIdx.x] = shq[0]; }
}

// ---------------------------------------------------------------------------
// K2: mu/inv_std finalize (redundant per block) + logits + sigmoid + partials
// float4 vectorized.
// ---------------------------------------------------------------------------
__global__ __launch_bounds__(TPB) void k_logits(
    const float* __restrict__ bw, const float* __restrict__ bb,
    float* __restrict__ out, int E)
{
    __shared__ double sh1[TPB], shq[TPB];
    double t1 = 0.0, t2 = 0.0;
    for (int i = threadIdx.x; i < NB; i += TPB) { t1 += g_p1[i]; t2 += g_p2[i]; }
    sh1[threadIdx.x] = t1; shq[threadIdx.x] = t2;
    __syncthreads();
    for (int st = TPB / 2; st; st >>= 1) {
        if (threadIdx.x < st) {
            sh1[threadIdx.x] += sh1[threadIdx.x + st];
            shq[threadIdx.x] += shq[threadIdx.x + st];
        }
        __syncthreads();
    }
    __shared__ float s_mu, s_inv;
    if (threadIdx.x == 0) {
        double mu  = sh1[0] / (double)E;
        double var = shq[0] / (double)E - mu * mu;
        s_mu  = (float)mu;
        s_inv = (float)rsqrt(var + 1e-5);
    }
    __syncthreads();

    const float mu = s_mu, inv = s_inv;
    const float w = __ldg(bw), b = __ldg(bb);
    const float wi = w * inv;
    float* __restrict__ out_logit = out + 3LL * E;
    float4* __restrict__ lik4 = (float4*)g_lik;
    float4* __restrict__ lg4  = (float4*)out_logit;

    const int E4 = E >> 2;
    const int tid = blockIdx.x * TPB + threadIdx.x;
    double s = 0.0;

    for (int i = tid; i < E4; i += NTHREADS) {
        float4 l = lik4[i];
        float4 g;
        g.x = fmaf(wi, l.x - mu, b);
        g.y = fmaf(wi, l.y - mu, b);
        g.z = fmaf(wi, l.z - mu, b);
        g.w = fmaf(wi, l.w - mu, b);
        __stcs(lg4 + i, g);
        float4 sg;
        sg.x = 1.0f / (1.0f + __expf(-g.x));
        sg.y = 1.0f / (1.0f + __expf(-g.y));
        sg.z = 1.0f / (1.0f + __expf(-g.z));
        sg.w = 1.0f / (1.0f + __expf(-g.w));
        lik4[i] = sg;
        s += (double)((sg.x + sg.y) + (sg.z + sg.w));
    }
    // scalar tail
    for (int e = E4 * 4 + tid; e < E; e += NTHREADS) {
        float lg = fmaf(wi, g_lik[e] - mu, b);
        __stcs(out_logit + e, lg);
        float sg = 1.0f / (1.0f + __expf(-lg));
        g_lik[e] = sg;
        s += (double)sg;
    }

    sh1[threadIdx.x] = s;
    __syncthreads();
    for (int st = TPB / 2; st; st >>= 1) {
        if (threadIdx.x < st) sh1[threadIdx.x] += sh1[threadIdx.x + st];
        __syncthreads();
    }
    if (threadIdx.x == 0) g_p3[blockIdx.x] = sh1[0];
}

// ---------------------------------------------------------------------------
// K3: inv_mean finalize (redundant per block) + normalized edge weights
// ---------------------------------------------------------------------------
__global__ __launch_bounds__(TPB) void k_ew(float* __restrict__ out, int E)
{
    __shared__ double sh[TPB];
    double t = 0.0;
    for (int i = threadIdx.x; i < NB; i += TPB) t += g_p3[i];
    sh[threadIdx.x] = t;
    __syncthreads();
    for (int st = TPB / 2; st; st >>= 1) {
        if (threadIdx.x < st) sh[threadIdx.x] += sh[threadIdx.x + st];
        __syncthreads();
    }
    __shared__ float s_im;
    if (threadIdx.x == 0) s_im = (float)((double)E / sh[0]);
    __syncthreads();

    const float im = s_im;
    float4* __restrict__ ew4  = (float4*)(out + 2LL * E);
    const float4* __restrict__ lik4 = (const float4*)g_lik;

    const int E4 = E >> 2;
    const int tid = blockIdx.x * TPB + threadIdx.x;
    for (int i = tid; i < E4; i += NTHREADS) {
        float4 l = __ldcs(lik4 + i);
        l.x *= im; l.y *= im; l.z *= im; l.w *= im;
        __stcs(ew4 + i, l);
    }
    for (int e = E4 * 4 + tid; e < E; e += NTHREADS)
        __stcs(out + 2LL * E + e, g_lik[e] * im);
}

// ---------------------------------------------------------------------------
extern "C" void kernel_launch(void* const* d_in, const int* in_sizes, int n_in,
                              void* d_out, int out_size)
{
    const float* src = (const float*)d_in[0];
    const float* dst = (const float*)d_in[1];
    const int*   gr  = (const int*)d_in[2];
    const float* bw  = (const float*)d_in[3];
    const float* bb  = (const float*)d_in[4];
    float* out = (float*)d_out;

    const int E  = in_sizes[2] / 2;
    const int Nn = in_sizes[0] / DD;
    const int total = min(in_sizes[0], NMAX * DD);

    k_conv  <<<NB, TPB>>>(src, dst, total);
    k_edge  <<<NB, TPB>>>(gr, out, E, Nn);
    k_logits<<<NB, TPB>>>(bw, bb, out, E);
    k_ew    <<<NB, TPB>>>(out, E);
}